// round 4
// baseline (speedup 1.0000x reference)
#include <cuda_runtime.h>
#include <math.h>

#define NB 32
#define NT 36
#define NN 10000
#define NF 3
#define NH 10
#define NR 20
#define PRED_ELEMS (NB * NH * NN)   // 3,200,000
#define NQ (NN / 4)                 // 2500 float4-groups of nodes per (b)
#define ROW4 (NN * NF / 4)          // 7500 float4 per (b,t) row

// ---------------- device scratch (no allocations allowed) ----------------
__device__ float g_time_mean[NB * NN];   // [B, N]
__device__ float g_rsum[NB * NR];        // per (b, r) sum of valid time_means
__device__ float g_rcnt[NB * NR];        // per (b, r) count of valid time_means
__device__ float g_g1;                   // global nanmean of pred_speed
__device__ int   g_cid[NN];              // normalized int32 cluster ids
__device__ int   g_nan_count;            // number of all-NaN (b, n) cells
__device__ int   g_nan_list[NB * NN];    // packed b*NN+n of all-NaN cells

// ---------------- K0: zero accumulators + normalize cluster_id dtype ----------------
// 1 block, 1024 threads. Detects int64 vs int32 storage, then writes g_cid.
__global__ void __launch_bounds__(1024) k0_init(const int* __restrict__ cid32) {
    if (threadIdx.x < NB * NR) {
        g_rsum[threadIdx.x] = 0.0f;
        g_rcnt[threadIdx.x] = 0.0f;
    }
    if (threadIdx.x == 0) g_nan_count = 0;

    __shared__ int s_bad;
    if (threadIdx.x == 0) s_bad = 0;
    __syncthreads();
    // If data is int64 (values 0..19), every odd 32-bit word is 0.
    // Scan first NN/2 pairs so reads stay in-bounds for the int32 case.
    int bad = 0;
    for (int i = threadIdx.x; i < NN / 2; i += blockDim.x) {
        if (cid32[2 * i + 1] != 0) bad = 1;
    }
    if (bad) atomicOr(&s_bad, 1);
    __syncthreads();
    const int is64 = (s_bad == 0) ? 1 : 0;
    for (int i = threadIdx.x; i < NN; i += blockDim.x) {
        g_cid[i] = is64 ? cid32[2 * i] : cid32[i];
    }
}

// ---------------- K1: time-mean + region accumulation + pred broadcast ----------------
// grid: (ceil(NQ/256), NB), block: 256. Each thread owns 4 consecutive nodes.
__global__ void __launch_bounds__(256) k1_time_mean(
    const float4* __restrict__ seq4, float* __restrict__ out) {
    const int b = blockIdx.y;
    const int j = blockIdx.x * blockDim.x + threadIdx.x;   // float4-group index

    __shared__ float s_rsum[NR];
    __shared__ float s_rcnt[NR];
    if (threadIdx.x < NR) {
        s_rsum[threadIdx.x] = 0.0f;
        s_rcnt[threadIdx.x] = 0.0f;
    }
    __syncthreads();

    if (j < NQ) {
        const float4* base = seq4 + (size_t)b * NT * ROW4 + (size_t)j * 3;
        float s0 = 0.f, s1 = 0.f, s2 = 0.f, s3 = 0.f;
        float c0 = 0.f, c1 = 0.f, c2 = 0.f, c3 = 0.f;
#pragma unroll
        for (int t = 0; t < NT; t++) {
            // 48 contiguous bytes = 4 nodes x 3 channels; ch0 at .x .w .z .y
            float4 f0 = __ldg(base + (size_t)t * ROW4);
            float4 f1 = __ldg(base + (size_t)t * ROW4 + 1);
            float4 f2 = __ldg(base + (size_t)t * ROW4 + 2);
            float x0 = f0.x, x1 = f0.w, x2 = f1.z, x3 = f2.y;
            if (x0 == x0) { s0 += x0; c0 += 1.0f; }
            if (x1 == x1) { s1 += x1; c1 += 1.0f; }
            if (x2 == x2) { s2 += x2; c2 += 1.0f; }
            if (x3 == x3) { s3 += x3; c3 += 1.0f; }
        }
        float4 tm = make_float4(s0 / c0, s1 / c1, s2 / c2, s3 / c3); // 0/0 -> NaN

        // persist time_mean and broadcast the 10 horizon copies now (store
        // pipe is idle while loads wait on DRAM; NaNs fixed by K3 later)
        const int n0 = 4 * j;
        *(float4*)&g_time_mean[b * NN + n0] = tm;
#pragma unroll
        for (int h = 0; h < NH; h++) {
            *(float4*)&out[(size_t)(b * NH + h) * NN + n0] = tm;
        }

        // region accumulation (shared), NaN cells to compact list
        const float tms[4] = {tm.x, tm.y, tm.z, tm.w};
#pragma unroll
        for (int k = 0; k < 4; k++) {
            float v = tms[k];
            if (v == v) {
                atomicAdd(&s_rsum[g_cid[n0 + k]], v);
                atomicAdd(&s_rcnt[g_cid[n0 + k]], 1.0f);
            } else {
                int idx = atomicAdd(&g_nan_count, 1);
                g_nan_list[idx] = b * NN + n0 + k;
            }
        }
    }
    __syncthreads();
    if (threadIdx.x < NR) {
        atomicAdd(&g_rsum[b * NR + threadIdx.x], s_rsum[threadIdx.x]);
    } else if (threadIdx.x < 2 * NR) {
        int r = threadIdx.x - NR;
        atomicAdd(&g_rcnt[b * NR + r], s_rcnt[r]);
    }
}

// ---------------- K2: finalize regional, g1, g2; write out_regional ----------------
// 1 block, 640 threads (one per (b, r))
__global__ void __launch_bounds__(640) k2_finalize(float* __restrict__ out) {
    const int i = threadIdx.x;          // 0..639
    const int b = i / NR;
    const int r = i % NR;

    float rs = g_rsum[i];
    float rc = g_rcnt[i];
    float reg = rs / rc;                // NaN if region empty for this batch
    bool rv = (reg == reg);

    // v0/v1 -> g1 (valid-node sum/count); v2/v3 -> g2 (valid regional mean)
    float v0 = rs, v1 = rc;
    float v2 = rv ? reg : 0.0f, v3 = rv ? 1.0f : 0.0f;
#pragma unroll
    for (int o = 16; o > 0; o >>= 1) {
        v0 += __shfl_down_sync(0xFFFFFFFFu, v0, o);
        v1 += __shfl_down_sync(0xFFFFFFFFu, v1, o);
        v2 += __shfl_down_sync(0xFFFFFFFFu, v2, o);
        v3 += __shfl_down_sync(0xFFFFFFFFu, v3, o);
    }
    __shared__ float sw[20][4];
    const int w = i >> 5, l = i & 31;
    if (l == 0) { sw[w][0] = v0; sw[w][1] = v1; sw[w][2] = v2; sw[w][3] = v3; }
    __syncthreads();

    __shared__ float s_g2;
    if (w == 0) {
        float a0 = (l < 20) ? sw[l][0] : 0.0f;
        float a1 = (l < 20) ? sw[l][1] : 0.0f;
        float a2 = (l < 20) ? sw[l][2] : 0.0f;
        float a3 = (l < 20) ? sw[l][3] : 0.0f;
#pragma unroll
        for (int o = 16; o > 0; o >>= 1) {
            a0 += __shfl_down_sync(0xFFFFFFFFu, a0, o);
            a1 += __shfl_down_sync(0xFFFFFFFFu, a1, o);
            a2 += __shfl_down_sync(0xFFFFFFFFu, a2, o);
            a3 += __shfl_down_sync(0xFFFFFFFFu, a3, o);
        }
        if (l == 0) {
            g_g1 = a0 / a1;
            s_g2 = a2 / a3;
        }
    }
    __syncthreads();

    float val = rv ? reg : s_g2;
    float* outR = out + PRED_ELEMS;     // regional output follows pred output
#pragma unroll
    for (int h = 0; h < NH; h++) {
        outR[(b * NH + h) * NR + r] = val;
    }
}

// ---------------- K3: fix the (rare) all-NaN pred cells with g1 ----------------
// 1 block, 256 threads; normally zero iterations.
__global__ void __launch_bounds__(256) k3_fix(float* __restrict__ out) {
    const int cnt = g_nan_count;
    const float g1 = g_g1;
    for (int i = threadIdx.x; i < cnt; i += blockDim.x) {
        int bn = g_nan_list[i];
        int b = bn / NN, n = bn % NN;
#pragma unroll
        for (int h = 0; h < NH; h++) {
            out[(size_t)(b * NH + h) * NN + n] = g1;
        }
    }
}

// ---------------- launcher ----------------
extern "C" void kernel_launch(void* const* d_in, const int* in_sizes, int n_in,
                              void* d_out, int out_size) {
    const float4* seq4 = (const float4*)d_in[0];
    const int* cid = (const int*)d_in[1];   // int32 or int64 -- probed at runtime
    float* out = (float*)d_out;

    k0_init<<<1, 1024>>>(cid);

    dim3 grid((NQ + 255) / 256, NB);
    k1_time_mean<<<grid, 256>>>(seq4, out);
    k2_finalize<<<1, 640>>>(out);
    k3_fix<<<1, 256>>>(out);
}

// round 5
// speedup vs baseline: 1.7335x; 1.7335x over previous
#include <cuda_runtime.h>
#include <math.h>

#define NB 32
#define NT 36
#define NN 10000
#define NF 3
#define NH 10
#define NR 20
#define PRED_ELEMS (NB * NH * NN)   // 3,200,000

// ---------------- device scratch (zero-initialized at module load; ----------------
// ---------------- k2 restores zeros at the end of every launch)      ----------------
__device__ float g_rsum[NB * NR];        // per (b, r) sum of valid time_means
__device__ float g_rcnt[NB * NR];        // per (b, r) count of valid time_means
__device__ int   g_nan_count;            // number of all-NaN (b, n) cells
__device__ int   g_nan_list[NB * NN];    // packed b*NN+n of all-NaN cells

// ---------------- K1: time-mean + region accumulation + pred broadcast ----------------
// grid: (ceil(NN/256), NB), block 256; one thread per (b, n).
// Scalar stride-12B loads: warp covers 384 contiguous bytes per t -> 3 L1
// wavefronts per 384 B (optimal). All 36 loads independent -> deep MLP.
__global__ void __launch_bounds__(256) k1_time_mean(
    const float* __restrict__ seq, const int* __restrict__ cid32,
    float* __restrict__ out) {
    const int b = blockIdx.y;
    const int n = blockIdx.x * blockDim.x + threadIdx.x;

    __shared__ float s_rsum[NR];
    __shared__ float s_rcnt[NR];
    if (threadIdx.x < NR) {
        s_rsum[threadIdx.x] = 0.0f;
        s_rcnt[threadIdx.x] = 0.0f;
    }

    // int64-vs-int32 probe for cluster_id: if int64, all odd 32-bit words are 0.
    // Values are 0..19, so 64 odd words all zero under int32 has P = 20^-64.
    int bad = 0;
    if (threadIdx.x < 64) bad = (cid32[2 * threadIdx.x + 1] != 0);
    const int is64 = (__syncthreads_or(bad) == 0);   // also covers smem init sync

    if (n < NN) {
        const float* base = seq + (size_t)b * (NT * NN * NF) + (size_t)n * NF;
        float s = 0.0f, c = 0.0f;
#pragma unroll
        for (int t = 0; t < NT; t++) {
            float x = __ldg(base + (size_t)t * (NN * NF));
            if (x == x) { s += x; c += 1.0f; }
        }
        const float tm = s / c;             // 0/0 -> NaN when node all-NaN

        // broadcast the 10 horizon copies now (store pipe idle under load latency)
#pragma unroll
        for (int h = 0; h < NH; h++) {
            out[(size_t)(b * NH + h) * NN + n] = tm;
        }

        if (tm == tm) {
            const int r = is64 ? cid32[2 * n] : cid32[n];
            atomicAdd(&s_rsum[r], tm);
            atomicAdd(&s_rcnt[r], 1.0f);
        } else {
            int idx = atomicAdd(&g_nan_count, 1);
            g_nan_list[idx] = b * NN + n;
        }
    }
    __syncthreads();
    if (threadIdx.x < NR) {
        atomicAdd(&g_rsum[b * NR + threadIdx.x], s_rsum[threadIdx.x]);
    } else if (threadIdx.x < 2 * NR) {
        const int r = threadIdx.x - NR;
        atomicAdd(&g_rcnt[b * NR + r], s_rcnt[r]);
    }
}

// ---------------- K2: finalize regional + g1/g2, write out_regional, ----------------
// ---------------- fix NaN pred cells, re-zero accumulators           ----------------
// 1 block, 640 threads (one per (b, r)).
__global__ void __launch_bounds__(640) k2_finalize(float* __restrict__ out) {
    const int i = threadIdx.x;          // 0..639
    const int b = i / NR;
    const int r = i % NR;

    const float rs = g_rsum[i];
    const float rc = g_rcnt[i];
    const float reg = rs / rc;          // NaN if region empty for this batch
    const bool rv = (reg == reg);

    // v0/v1 -> g1 (valid-node sum/count); v2/v3 -> g2 (valid regional mean)
    float v0 = rs, v1 = rc;
    float v2 = rv ? reg : 0.0f, v3 = rv ? 1.0f : 0.0f;
#pragma unroll
    for (int o = 16; o > 0; o >>= 1) {
        v0 += __shfl_down_sync(0xFFFFFFFFu, v0, o);
        v1 += __shfl_down_sync(0xFFFFFFFFu, v1, o);
        v2 += __shfl_down_sync(0xFFFFFFFFu, v2, o);
        v3 += __shfl_down_sync(0xFFFFFFFFu, v3, o);
    }
    __shared__ float sw[20][4];
    const int w = i >> 5, l = i & 31;
    if (l == 0) { sw[w][0] = v0; sw[w][1] = v1; sw[w][2] = v2; sw[w][3] = v3; }
    __syncthreads();

    __shared__ float s_g1, s_g2;
    if (w == 0) {
        float a0 = (l < 20) ? sw[l][0] : 0.0f;
        float a1 = (l < 20) ? sw[l][1] : 0.0f;
        float a2 = (l < 20) ? sw[l][2] : 0.0f;
        float a3 = (l < 20) ? sw[l][3] : 0.0f;
#pragma unroll
        for (int o = 16; o > 0; o >>= 1) {
            a0 += __shfl_down_sync(0xFFFFFFFFu, a0, o);
            a1 += __shfl_down_sync(0xFFFFFFFFu, a1, o);
            a2 += __shfl_down_sync(0xFFFFFFFFu, a2, o);
            a3 += __shfl_down_sync(0xFFFFFFFFu, a3, o);
        }
        if (l == 0) {
            s_g1 = a0 / a1;
            s_g2 = a2 / a3;
        }
    }
    __syncthreads();

    // regional output (NaN regions -> g2)
    const float val = rv ? reg : s_g2;
    float* outR = out + PRED_ELEMS;
#pragma unroll
    for (int h = 0; h < NH; h++) {
        outR[(b * NH + h) * NR + r] = val;
    }

    // fix the (statistically nonexistent) all-NaN pred cells with g1
    const int cnt = g_nan_count;
    const float g1 = s_g1;
    for (int idx = i; idx < cnt; idx += 640) {
        const int bn = g_nan_list[idx];
        const int bb = bn / NN, nn = bn % NN;
#pragma unroll
        for (int h = 0; h < NH; h++) {
            out[(size_t)(bb * NH + h) * NN + nn] = g1;
        }
    }

    // restore zeros for the next graph replay (module-load init covers call #1)
    __syncthreads();
    g_rsum[i] = 0.0f;
    g_rcnt[i] = 0.0f;
    if (i == 0) g_nan_count = 0;
}

// ---------------- launcher ----------------
extern "C" void kernel_launch(void* const* d_in, const int* in_sizes, int n_in,
                              void* d_out, int out_size) {
    const float* seq = (const float*)d_in[0];
    const int* cid = (const int*)d_in[1];   // int32 or int64 -- probed in-kernel
    float* out = (float*)d_out;

    dim3 grid((NN + 255) / 256, NB);
    k1_time_mean<<<grid, 256>>>(seq, cid, out);
    k2_finalize<<<1, 640>>>(out);
}

// round 6
// speedup vs baseline: 1.7452x; 1.0067x over previous
#include <cuda_runtime.h>
#include <math.h>

#define NB 32
#define NT 36
#define NN 10000
#define NF 3
#define NH 10
#define NR 20
#define PRED_ELEMS (NB * NH * NN)   // 3,200,000
#define NBLK_X ((NN + 255) / 256)   // 40
#define NBLOCKS (NBLK_X * NB)       // 1280

// ---------------- device scratch (zero-initialized at module load; ----------------
// ---------------- last block restores zeros every launch -> replay-safe) ----------
__device__ float g_rsum[NB * NR];        // per (b, r) sum of valid time_means
__device__ float g_rcnt[NB * NR];        // per (b, r) count of valid time_means
__device__ int   g_nan_count;            // number of all-NaN (b, n) cells
__device__ int   g_nan_list[NB * NN];    // packed b*NN+n of all-NaN cells
__device__ unsigned int g_done;          // completed-block ticket

// ---------------- K1: everything in one kernel ----------------
// grid: (40, 32), block 256; one thread per (b, n).
// Scalar stride-12B loads: warp covers 384 contiguous bytes per t -> 3 L1
// wavefronts per 384 B (optimal). 36 independent loads -> deep MLP.
// The last block to finish performs the finalization (regional means, g1/g2,
// out_regional, NaN fixup) and re-zeroes the scratch for graph replay.
__global__ void __launch_bounds__(256) k1_fused(
    const float* __restrict__ seq, const int* __restrict__ cid32,
    float* __restrict__ out) {
    const int b = blockIdx.y;
    const int n = blockIdx.x * blockDim.x + threadIdx.x;
    const int tid = threadIdx.x;

    __shared__ float s_rsum[NR];
    __shared__ float s_rcnt[NR];
    if (tid < NR) {
        s_rsum[tid] = 0.0f;
        s_rcnt[tid] = 0.0f;
    }

    // int64-vs-int32 probe for cluster_id: if int64, all odd 32-bit words are 0.
    // Values are 0..19, so 64 odd words all zero under int32 has P = 20^-64.
    int bad = 0;
    if (tid < 64) bad = (cid32[2 * tid + 1] != 0);
    const int is64 = (__syncthreads_or(bad) == 0);   // also covers smem init sync

    if (n < NN) {
        const float* base = seq + (size_t)b * (NT * NN * NF) + (size_t)n * NF;
        float s = 0.0f, c = 0.0f;
#pragma unroll
        for (int t = 0; t < NT; t++) {
            float x = __ldg(base + (size_t)t * (NN * NF));
            if (x == x) { s += x; c += 1.0f; }
        }
        const float tm = s / c;             // 0/0 -> NaN when node all-NaN

        // broadcast the 10 horizon copies (store pipe idle under load latency)
#pragma unroll
        for (int h = 0; h < NH; h++) {
            out[(size_t)(b * NH + h) * NN + n] = tm;
        }

        if (tm == tm) {
            const int r = is64 ? cid32[2 * n] : cid32[n];
            atomicAdd(&s_rsum[r], tm);
            atomicAdd(&s_rcnt[r], 1.0f);
        } else {
            int idx = atomicAdd(&g_nan_count, 1);
            g_nan_list[idx] = b * NN + n;
        }
    }
    __syncthreads();
    if (tid < NR) {
        atomicAdd(&g_rsum[b * NR + tid], s_rsum[tid]);
    } else if (tid < 2 * NR) {
        const int r = tid - NR;
        atomicAdd(&g_rcnt[b * NR + r], s_rcnt[r]);
    }

    // ---------------- last-block finalization ----------------
    __threadfence();                       // make our global atomics visible
    __shared__ unsigned int s_ticket;
    __syncthreads();                       // all block's atomics issued before ticket
    if (tid == 0) s_ticket = atomicAdd(&g_done, 1u);
    __syncthreads();
    if (s_ticket != NBLOCKS - 1) return;   // not the last block

    // --- we are the last block: all g_rsum/g_rcnt/g_nan_* updates are visible ---
    // Reduce 4 quantities over the 640 (b, r) cells with 256 threads:
    // v0/v1 -> g1 (valid-node sum/count); v2/v3 -> g2 (mean of valid regional)
    float v0 = 0.f, v1 = 0.f, v2 = 0.f, v3 = 0.f;
    for (int i = tid; i < NB * NR; i += 256) {
        const float rs = g_rsum[i];
        const float rc = g_rcnt[i];
        const float reg = rs / rc;
        v0 += rs; v1 += rc;
        if (reg == reg) { v2 += reg; v3 += 1.0f; }
    }
#pragma unroll
    for (int o = 16; o > 0; o >>= 1) {
        v0 += __shfl_down_sync(0xFFFFFFFFu, v0, o);
        v1 += __shfl_down_sync(0xFFFFFFFFu, v1, o);
        v2 += __shfl_down_sync(0xFFFFFFFFu, v2, o);
        v3 += __shfl_down_sync(0xFFFFFFFFu, v3, o);
    }
    __shared__ float sw[8][4];
    const int w = tid >> 5, l = tid & 31;
    if (l == 0) { sw[w][0] = v0; sw[w][1] = v1; sw[w][2] = v2; sw[w][3] = v3; }
    __syncthreads();
    __shared__ float s_g1, s_g2;
    if (w == 0) {
        float a0 = (l < 8) ? sw[l][0] : 0.0f;
        float a1 = (l < 8) ? sw[l][1] : 0.0f;
        float a2 = (l < 8) ? sw[l][2] : 0.0f;
        float a3 = (l < 8) ? sw[l][3] : 0.0f;
#pragma unroll
        for (int o = 4; o > 0; o >>= 1) {
            a0 += __shfl_down_sync(0xFFFFFFFFu, a0, o);
            a1 += __shfl_down_sync(0xFFFFFFFFu, a1, o);
            a2 += __shfl_down_sync(0xFFFFFFFFu, a2, o);
            a3 += __shfl_down_sync(0xFFFFFFFFu, a3, o);
        }
        if (l == 0) {
            s_g1 = a0 / a1;
            s_g2 = a2 / a3;
        }
    }
    __syncthreads();
    const float g1 = s_g1, g2 = s_g2;

    // regional output (NaN regions -> g2), then re-zero accumulators
    float* outR = out + PRED_ELEMS;
    for (int i = tid; i < NB * NR; i += 256) {
        const int bb = i / NR, rr = i % NR;
        const float reg = g_rsum[i] / g_rcnt[i];
        const float val = (reg == reg) ? reg : g2;
#pragma unroll
        for (int h = 0; h < NH; h++) {
            outR[(bb * NH + h) * NR + rr] = val;
        }
        g_rsum[i] = 0.0f;               // reset for next graph replay
        g_rcnt[i] = 0.0f;
    }

    // fix the (statistically nonexistent) all-NaN pred cells with g1
    const int cnt = g_nan_count;
    for (int idx = tid; idx < cnt; idx += 256) {
        const int bn = g_nan_list[idx];
        const int bb = bn / NN, nn = bn % NN;
#pragma unroll
        for (int h = 0; h < NH; h++) {
            out[(size_t)(bb * NH + h) * NN + nn] = g1;
        }
    }
    if (tid == 0) {
        g_nan_count = 0;
        g_done = 0;                     // reset ticket for next replay
    }
}

// ---------------- launcher ----------------
extern "C" void kernel_launch(void* const* d_in, const int* in_sizes, int n_in,
                              void* d_out, int out_size) {
    const float* seq = (const float*)d_in[0];
    const int* cid = (const int*)d_in[1];   // int32 or int64 -- probed in-kernel
    float* out = (float*)d_out;

    dim3 grid(NBLK_X, NB);
    k1_fused<<<grid, 256>>>(seq, cid, out);
}